// round 1
// baseline (speedup 1.0000x reference)
#include <cuda_runtime.h>
#include <cuda_bf16.h>

// Problem constants: B=16, C=8, H=512, W=512
#define HW      262144      // H*W
#define HWQ     65536       // HW / 4  (float4 per channel plane)
#define CHW     2097152     // C*HW
#define NGRP    1048576     // total pixels / 4
#define INV_TOT (1.0f / 4194304.0f)

#define HIST_BLOCKS  304
#define HIST_THREADS 512

__device__ unsigned int g_hist[8];

__global__ void cb_zero() {
    if (threadIdx.x < 8) g_hist[threadIdx.x] = 0u;
}

// One pixel: tag each channel value's low 3 mantissa bits with the channel
// index, take fmax tree (winner's low bits == argmax index), bump a packed
// 8-bit-lane counter. accA holds bins 0-3, accB bins 4-7.
__device__ __forceinline__ void cb_pix(
    float x0, float x1, float x2, float x3,
    float x4, float x5, float x6, float x7,
    unsigned& accA, unsigned& accB)
{
    unsigned e0 =  __float_as_uint(x0) & 0xFFFFFFF8u;
    unsigned e1 = (__float_as_uint(x1) & 0xFFFFFFF8u) | 1u;
    unsigned e2 = (__float_as_uint(x2) & 0xFFFFFFF8u) | 2u;
    unsigned e3 = (__float_as_uint(x3) & 0xFFFFFFF8u) | 3u;
    unsigned e4 = (__float_as_uint(x4) & 0xFFFFFFF8u) | 4u;
    unsigned e5 = (__float_as_uint(x5) & 0xFFFFFFF8u) | 5u;
    unsigned e6 = (__float_as_uint(x6) & 0xFFFFFFF8u) | 6u;
    unsigned e7 = (__float_as_uint(x7) & 0xFFFFFFF8u) | 7u;

    float m01 = fmaxf(__uint_as_float(e0), __uint_as_float(e1));
    float m23 = fmaxf(__uint_as_float(e2), __uint_as_float(e3));
    float m45 = fmaxf(__uint_as_float(e4), __uint_as_float(e5));
    float m67 = fmaxf(__uint_as_float(e6), __uint_as_float(e7));
    float m03 = fmaxf(m01, m23);
    float m47 = fmaxf(m45, m67);
    float m   = fmaxf(m03, m47);

    unsigned w   = __float_as_uint(m);          // low 3 bits = argmax index
    unsigned inc = 1u << ((w & 3u) << 3);       // 8-bit lane within acc
    if (w & 4u) accB += inc; else accA += inc;
}

__global__ void __launch_bounds__(HIST_THREADS, 2)
cb_hist(const float* __restrict__ in)
{
    unsigned accA = 0u, accB = 0u;
    unsigned tid    = blockIdx.x * blockDim.x + threadIdx.x;
    unsigned stride = gridDim.x * blockDim.x;

    for (unsigned g = tid; g < NGRP; g += stride) {
        unsigned b = g >> 16;                 // image index (HWQ groups/image)
        unsigned q = g & 0xFFFFu;             // float4 index within plane
        const float4* p =
            reinterpret_cast<const float4*>(in + (size_t)b * CHW) + q;

        float4 v0 = __ldg(p + 0 * HWQ);
        float4 v1 = __ldg(p + 1 * HWQ);
        float4 v2 = __ldg(p + 2 * HWQ);
        float4 v3 = __ldg(p + 3 * HWQ);
        float4 v4 = __ldg(p + 4 * HWQ);
        float4 v5 = __ldg(p + 5 * HWQ);
        float4 v6 = __ldg(p + 6 * HWQ);
        float4 v7 = __ldg(p + 7 * HWQ);

        cb_pix(v0.x, v1.x, v2.x, v3.x, v4.x, v5.x, v6.x, v7.x, accA, accB);
        cb_pix(v0.y, v1.y, v2.y, v3.y, v4.y, v5.y, v6.y, v7.y, accA, accB);
        cb_pix(v0.z, v1.z, v2.z, v3.z, v4.z, v5.z, v6.z, v7.z, accA, accB);
        cb_pix(v0.w, v1.w, v2.w, v3.w, v4.w, v5.w, v6.w, v7.w, accA, accB);
    }

    // Unpack 8-bit lanes, warp-reduce (REDUX), shared-combine, global atomics.
    unsigned c[8];
    c[0] =  accA        & 255u;
    c[1] = (accA >>  8) & 255u;
    c[2] = (accA >> 16) & 255u;
    c[3] =  accA >> 24;
    c[4] =  accB        & 255u;
    c[5] = (accB >>  8) & 255u;
    c[6] = (accB >> 16) & 255u;
    c[7] =  accB >> 24;

    __shared__ unsigned sh[8];
    if (threadIdx.x < 8) sh[threadIdx.x] = 0u;
    __syncthreads();

#pragma unroll
    for (int i = 0; i < 8; i++) {
        unsigned t = __reduce_add_sync(0xffffffffu, c[i]);
        if ((threadIdx.x & 31u) == 0u) atomicAdd(&sh[i], t);
    }
    __syncthreads();

    if (threadIdx.x < 8) atomicAdd(&g_hist[threadIdx.x], sh[threadIdx.x]);
}

__global__ void cb_final(const float* __restrict__ prev,
                         float* __restrict__ out, int out_size)
{
    if (threadIdx.x == 0) {
        float dist[8];
        float ss = 0.0f;
#pragma unroll
        for (int c = 0; c < 8; c++) {
            float d = prev[c] * 0.99f + 0.01f * ((float)g_hist[c] * INV_TOT);
            dist[c] = d;
            float t = (d - 0.125f) * (1.0f / 0.875f);
            ss += t * t;
        }
        float bal = sqrtf(ss);
        if (out_size >= 9) {
            out[0] = bal;
#pragma unroll
            for (int c = 0; c < 8; c++) out[1 + c] = dist[c];
        } else if (out_size == 8) {
#pragma unroll
            for (int c = 0; c < 8; c++) out[c] = dist[c];
        } else if (out_size >= 1) {
            out[0] = bal;
        }
    }
}

extern "C" void kernel_launch(void* const* d_in, const int* in_sizes, int n_in,
                              void* d_out, int out_size)
{
    // Robust input identification: masks is the 33.5M-element tensor.
    const float* masks = (const float*)d_in[0];
    const float* prev  = (const float*)d_in[1];
    if (n_in >= 2 && in_sizes[0] == 8) {
        masks = (const float*)d_in[1];
        prev  = (const float*)d_in[0];
    }

    cb_zero<<<1, 32>>>();
    cb_hist<<<HIST_BLOCKS, HIST_THREADS>>>(masks);
    cb_final<<<1, 32>>>(prev, (float*)d_out, out_size);
}

// round 2
// speedup vs baseline: 1.0654x; 1.0654x over previous
#include <cuda_runtime.h>
#include <cuda_bf16.h>

// Problem constants: B=16, C=8, H=512, W=512
#define HWQ     65536        // H*W / 4  (float4 per channel plane)
#define NGRP    1048576      // total pixels / 4
#define INV_TOT (1.0f / 4194304.0f)

#define NBLOCKS  512
#define NTHREADS 256
// NBLOCKS*NTHREADS = 131072 = 2^17  ->  exactly 8 groups per thread.
// Group stride 131072 = 2 image planes -> constant float4 address stride:
//   addr(g) = (g>>16)*8*HWQ + (g&65535);  delta per iter = 2*8*HWQ + 0... 
//   = 131072 groups => b += 2, q same => delta = 2*524288 = 1048576 float4.
#define ITER_STRIDE4 1048576u

__device__ unsigned int g_hist[8];
__device__ unsigned int g_done;

// One pixel: tag each channel value's low 3 mantissa bits with the channel
// index (1 LOP3 each), 7-deep fmax tree -> winner's low 3 bits = argmax.
// Bump an 8-bit-lane packed counter (accA bins 0-3, accB bins 4-7).
// Max 32 pixels/thread per bin, no overflow.
__device__ __forceinline__ void cb_pix(
    float x0, float x1, float x2, float x3,
    float x4, float x5, float x6, float x7,
    unsigned& accA, unsigned& accB)
{
    unsigned e0 =  __float_as_uint(x0) & 0xFFFFFFF8u;
    unsigned e1 = (__float_as_uint(x1) & 0xFFFFFFF8u) | 1u;
    unsigned e2 = (__float_as_uint(x2) & 0xFFFFFFF8u) | 2u;
    unsigned e3 = (__float_as_uint(x3) & 0xFFFFFFF8u) | 3u;
    unsigned e4 = (__float_as_uint(x4) & 0xFFFFFFF8u) | 4u;
    unsigned e5 = (__float_as_uint(x5) & 0xFFFFFFF8u) | 5u;
    unsigned e6 = (__float_as_uint(x6) & 0xFFFFFFF8u) | 6u;
    unsigned e7 = (__float_as_uint(x7) & 0xFFFFFFF8u) | 7u;

    float m01 = fmaxf(__uint_as_float(e0), __uint_as_float(e1));
    float m23 = fmaxf(__uint_as_float(e2), __uint_as_float(e3));
    float m45 = fmaxf(__uint_as_float(e4), __uint_as_float(e5));
    float m67 = fmaxf(__uint_as_float(e6), __uint_as_float(e7));
    float m03 = fmaxf(m01, m23);
    float m47 = fmaxf(m45, m67);
    float m   = fmaxf(m03, m47);

    unsigned w   = __float_as_uint(m);          // low 3 bits = argmax index
    unsigned inc = 1u << ((w & 3u) << 3);       // 8-bit lane select
    if (w & 4u) accB += inc; else accA += inc;
}

__global__ void __launch_bounds__(NTHREADS, 4)
cb_fused(const float* __restrict__ in, const float* __restrict__ prev,
         float* __restrict__ out, int out_size)
{
    const unsigned t  = blockIdx.x * NTHREADS + threadIdx.x;
    const unsigned b0 = t >> 16;            // starting image (0 or 1)
    const unsigned q  = t & 65535u;         // float4 offset within plane
    const float4* p = reinterpret_cast<const float4*>(in)
                      + (size_t)b0 * (8u * HWQ) + q;

    unsigned accA = 0u, accB = 0u;

#pragma unroll 1
    for (int i = 0; i < 8; i++) {
        float4 v0 = __ldg(p + 0 * HWQ);
        float4 v1 = __ldg(p + 1 * HWQ);
        float4 v2 = __ldg(p + 2 * HWQ);
        float4 v3 = __ldg(p + 3 * HWQ);
        float4 v4 = __ldg(p + 4 * HWQ);
        float4 v5 = __ldg(p + 5 * HWQ);
        float4 v6 = __ldg(p + 6 * HWQ);
        float4 v7 = __ldg(p + 7 * HWQ);
        p += ITER_STRIDE4;

        cb_pix(v0.x, v1.x, v2.x, v3.x, v4.x, v5.x, v6.x, v7.x, accA, accB);
        cb_pix(v0.y, v1.y, v2.y, v3.y, v4.y, v5.y, v6.y, v7.y, accA, accB);
        cb_pix(v0.z, v1.z, v2.z, v3.z, v4.z, v5.z, v6.z, v7.z, accA, accB);
        cb_pix(v0.w, v1.w, v2.w, v3.w, v4.w, v5.w, v6.w, v7.w, accA, accB);
    }

    // ---- per-block reduction: unpack 8-bit lanes, REDUX per warp, shared ----
    __shared__ unsigned sh[8];
    if (threadIdx.x < 8) sh[threadIdx.x] = 0u;
    __syncthreads();

    unsigned c[8];
    c[0] =  accA        & 255u;
    c[1] = (accA >>  8) & 255u;
    c[2] = (accA >> 16) & 255u;
    c[3] =  accA >> 24;
    c[4] =  accB        & 255u;
    c[5] = (accB >>  8) & 255u;
    c[6] = (accB >> 16) & 255u;
    c[7] =  accB >> 24;

#pragma unroll
    for (int i = 0; i < 8; i++) {
        unsigned s = __reduce_add_sync(0xffffffffu, c[i]);
        if ((threadIdx.x & 31u) == 0u) atomicAdd(&sh[i], s);
    }
    __syncthreads();

    // ---- global combine + completion protocol ----
    if (threadIdx.x < 8) {
        atomicAdd(&g_hist[threadIdx.x], sh[threadIdx.x]);
        __threadfence();                 // hist visible before done-increment
    }
    __syncthreads();

    if (threadIdx.x == 0) {
        unsigned old = atomicAdd(&g_done, 1u);
        if (old == NBLOCKS - 1) {
            // last block: read-and-reset histogram, compute final output
            float dist[8];
            float ss = 0.0f;
#pragma unroll
            for (int cc = 0; cc < 8; cc++) {
                unsigned h = atomicExch(&g_hist[cc], 0u);   // read + reset
                float d = prev[cc] * 0.99f + 0.01f * ((float)h * INV_TOT);
                dist[cc] = d;
                float u = (d - 0.125f) * (1.0f / 0.875f);
                ss += u * u;
            }
            float bal = sqrtf(ss);
            if (out_size >= 9) {
                out[0] = bal;
#pragma unroll
                for (int cc = 0; cc < 8; cc++) out[1 + cc] = dist[cc];
            } else if (out_size == 8) {
#pragma unroll
                for (int cc = 0; cc < 8; cc++) out[cc] = dist[cc];
            } else if (out_size >= 1) {
                out[0] = bal;
            }
            atomicExch(&g_done, 0u);     // reset for next graph replay
        }
    }
}

extern "C" void kernel_launch(void* const* d_in, const int* in_sizes, int n_in,
                              void* d_out, int out_size)
{
    // masks is the 33.5M-element tensor; prev_dist has 8 elements.
    const float* masks = (const float*)d_in[0];
    const float* prev  = (const float*)d_in[1];
    if (n_in >= 2 && in_sizes[0] == 8) {
        masks = (const float*)d_in[1];
        prev  = (const float*)d_in[0];
    }

    cb_fused<<<NBLOCKS, NTHREADS>>>(masks, prev, (float*)d_out, out_size);
}